// round 13
// baseline (speedup 1.0000x reference)
#include <cuda_runtime.h>
#include <cuda_bf16.h>
#include <cuda_fp16.h>
#include <cstdint>
#include <math.h>

#define NND 100000
#define NE  1600000
#define DF  128
#define HEADS 4
#define NG  64
#define NCLS 10
#define NEG 0.2f
#define SCANB 512

// ---------------- scratch ----------------------------------------------------
__device__ __align__(16) __half g_XWh[NND * DF];   // fp16 x@W (messages+self)
__device__ __align__(16) __half g_Hh [NND * DF];   // fp16 relu(layer output)
__device__ __align__(16) float  g_al[NND * HEADS];
__device__ __align__(16) float  g_ar[NND * HEADS];
__device__ unsigned g_gmaxenc[3][HEADS];
__device__ int   g_deg[NND];
__device__ int   g_rowptr[NND + 1];
__device__ int   g_pos[NND];
__device__ int   g_bsum[(NND + SCANB - 1) / SCANB];
__device__ int   g_csr[NE];
__device__ float g_pool[NG * DF];
__device__ int   g_cnt[NG];
__device__ __align__(16) uint4 g_WfT[3][2048];     // fp16 W^T swizzled

// ---------------- helpers ----------------------------------------------------
__device__ __forceinline__ float lrelu(float x) { return x > 0.f ? x : NEG * x; }
__device__ __forceinline__ unsigned fenc(float f) {
    unsigned u = __float_as_uint(f);
    return (u & 0x80000000u) ? ~u : (u | 0x80000000u);
}
__device__ __forceinline__ float fdec(unsigned u) {
    return (u & 0x80000000u) ? __uint_as_float(u & 0x7FFFFFFFu)
                             : __uint_as_float(~u);
}
__device__ __forceinline__ float sel4(float4 v, int h) {
    return h == 0 ? v.x : h == 1 ? v.y : h == 2 ? v.z : v.w;
}
__device__ __forceinline__ void redAdd4(float* p, float4 v) {
    asm volatile("red.global.add.v4.f32 [%0], {%1,%2,%3,%4};"
                 :: "l"(p), "f"(v.x), "f"(v.y), "f"(v.z), "f"(v.w) : "memory");
}
__device__ __forceinline__ void stcs4(float* p, float4 v) {
    asm volatile("st.global.cs.v4.f32 [%0], {%1,%2,%3,%4};"
                 :: "l"(p), "f"(v.x), "f"(v.y), "f"(v.z), "f"(v.w) : "memory");
}
__device__ __forceinline__ void stcs4u(void* p, uint4 u) {
    asm volatile("st.global.cs.v4.u32 [%0], {%1,%2,%3,%4};"
                 :: "l"(p), "r"(u.x), "r"(u.y), "r"(u.z), "r"(u.w) : "memory");
}
__device__ __forceinline__ uint32_t smem_u32(const void* p) {
    uint32_t a;
    asm("{ .reg .u64 t; cvta.to.shared.u64 t, %1; cvt.u32.u64 %0, t; }" : "=r"(a) : "l"(p));
    return a;
}
__device__ __forceinline__ void ldm4(uint32_t& r0, uint32_t& r1, uint32_t& r2,
                                     uint32_t& r3, uint32_t addr) {
    asm volatile("ldmatrix.sync.aligned.m8n8.x4.shared.b16 {%0,%1,%2,%3}, [%4];"
                 : "=r"(r0), "=r"(r1), "=r"(r2), "=r"(r3) : "r"(addr));
}
__device__ __forceinline__ void mma16816f(float* d, uint32_t a0, uint32_t a1,
                                          uint32_t a2, uint32_t a3,
                                          uint32_t b0, uint32_t b1) {
    asm volatile(
        "mma.sync.aligned.m16n8k16.row.col.f32.f16.f16.f32 "
        "{%0,%1,%2,%3}, {%4,%5,%6,%7}, {%8,%9}, {%0,%1,%2,%3};"
        : "+f"(d[0]), "+f"(d[1]), "+f"(d[2]), "+f"(d[3])
        : "r"(a0), "r"(a1), "r"(a2), "r"(a3), "r"(b0), "r"(b1));
}

union H16x8 { __half h[8]; uint4 u; };

// ---------------- weight prep + gmax zero -------------------------------------
__global__ void prep_all(const float* __restrict__ W0, const float* __restrict__ W1,
                         const float* __restrict__ W2) {
    if (blockIdx.x == 0 && threadIdx.x < 12)
        ((unsigned*)g_gmaxenc)[threadIdx.x] = 0u;
    int L = blockIdx.x >> 3;
    int i = (blockIdx.x & 7) * 256 + threadIdx.x;
    const float* W = (L == 0) ? W0 : (L == 1) ? W1 : W2;
    int nn = i >> 4, c = i & 15;
    H16x8 F;
#pragma unroll
    for (int j = 0; j < 8; j++)
        F.h[j] = __float2half(W[(c * 8 + j) * 128 + nn]);
    g_WfT[L][nn * 16 + (c ^ (nn & 7))] = F.u;
}

// ---------------- fp16 HMMA GEMM + fused al/ar + almax -----------------------
#define GS_A   0
#define GS_W   16384
#define GS_ATT 49152
#define GS_TOT 50176
#define HS_STRIDE 136

__global__ void __launch_bounds__(256, 3) gemm_mma(
    const void* __restrict__ Ain, int aHalf, const uint4* __restrict__ WfT,
    const float* __restrict__ attl, const float* __restrict__ attr,
    int n, int Lidx) {
    extern __shared__ char smem[];
    __shared__ unsigned smax[4];
    uint32_t sb = smem_u32(smem);
    int tid = threadIdx.x, w = tid >> 5, l = tid & 31;
    int rg = w & 3, ch = w >> 2;
    int row0 = blockIdx.x * 64;

    {
        uint4* wf = (uint4*)(smem + GS_W);
        for (int i = tid; i < 2048; i += 256) wf[i] = WfT[i];
    }
    if (aHalf) {
        const __half* Ah = (const __half*)Ain;
        for (int i = tid; i < 1024; i += 256) {
            int r = i >> 4, c = i & 15;
            int row = row0 + r;
            uint4 u = make_uint4(0u, 0u, 0u, 0u);
            if (row < n) u = __ldcs((const uint4*)&Ah[row * 128 + c * 8]);
            *(uint4*)(smem + GS_A + r * 256 + ((c ^ (r & 7)) << 4)) = u;
        }
    } else {
        const float* A = (const float*)Ain;
        for (int i = tid; i < 1024; i += 256) {
            int r = i >> 4, c = i & 15;
            int row = row0 + r;
            float4 v0 = make_float4(0.f, 0.f, 0.f, 0.f), v1 = v0;
            if (row < n) {
                v0 = __ldcs((const float4*)&A[row * 128 + c * 8]);
                v1 = __ldcs((const float4*)&A[row * 128 + c * 8 + 4]);
            }
            H16x8 F;
            F.h[0] = __float2half(v0.x); F.h[1] = __float2half(v0.y);
            F.h[2] = __float2half(v0.z); F.h[3] = __float2half(v0.w);
            F.h[4] = __float2half(v1.x); F.h[5] = __float2half(v1.y);
            F.h[6] = __float2half(v1.z); F.h[7] = __float2half(v1.w);
            *(uint4*)(smem + GS_A + r * 256 + ((c ^ (r & 7)) << 4)) = F.u;
        }
    }
    __syncthreads();

    int aRow = rg * 16 + ((l >> 3) & 1) * 8 + (l & 7);
    int aChk = (l >> 4) & 1;
    uint32_t aBase = sb + GS_A + aRow * 256;
    int aXor = aRow & 7;
    int bRowL = ((l >> 4) & 1) * 8 + (l & 7);
    int bChk = (l >> 3) & 1;

    float acc[32];
#pragma unroll
    for (int i = 0; i < 32; i++) acc[i] = 0.f;

#pragma unroll
    for (int ks = 0; ks < 8; ks++) {
        uint32_t a0, a1, a2, a3;
        ldm4(a0, a1, a2, a3, aBase + (((2 * ks + aChk) ^ aXor) << 4));
#pragma unroll
        for (int p = 0; p < 4; p++) {
            int bRow = ch * 64 + p * 16 + bRowL;
            uint32_t bAddr = sb + GS_W + bRow * 256
                           + (((2 * ks + bChk) ^ (bRow & 7)) << 4);
            uint32_t b0, b1, b2, b3;
            ldm4(b0, b1, b2, b3, bAddr);
            mma16816f(&acc[(2 * p) * 4],     a0, a1, a2, a3, b0, b1);
            mma16816f(&acc[(2 * p + 1) * 4], a0, a1, a2, a3, b2, b3);
        }
    }
    __syncthreads();

    __half* Hs = (__half*)smem;
    float* att = (float*)(smem + GS_ATT);
    att[tid] = (tid < 128) ? attl[tid] : attr[tid - 128];
    if (tid < 4) smax[tid] = 0u;
    {
        int r1 = rg * 16 + (l >> 2);
#pragma unroll
        for (int nt = 0; nt < 8; nt++) {
            int p = nt >> 1, t = nt & 1;
            int col = ch * 64 + p * 16 + t * 8 + (l & 3) * 2;
            float* d = &acc[nt * 4];
            __half2 lo = __floats2half2_rn(d[0], d[1]);
            __half2 hi = __floats2half2_rn(d[2], d[3]);
            *(__half2*)&Hs[r1 * HS_STRIDE + col]       = lo;
            *(__half2*)&Hs[(r1 + 8) * HS_STRIDE + col] = hi;
        }
    }
    __syncthreads();

    for (int i = tid; i < 1024; i += 256) {
        int r = i >> 4, c = i & 15;
        int row = row0 + r;
        if (row < n)
            *(uint4*)&g_XWh[row * 128 + c * 8] =
                *(uint4*)&Hs[r * HS_STRIDE + c * 8];
    }
    if (tid < 128) {
        int half_ = tid >> 6;
        int r = tid & 63;
        int row = row0 + r;
        if (row < n) {
            const float* av = att + half_ * 128;
            const __half2* hr = (const __half2*)&Hs[r * HS_STRIDE];
            float d0 = 0.f, d1 = 0.f, d2 = 0.f, d3 = 0.f;
#pragma unroll 8
            for (int c = 0; c < 16; c++) {
                float2 f0 = __half22float2(hr[c]);
                float2 f1 = __half22float2(hr[16 + c]);
                float2 f2 = __half22float2(hr[32 + c]);
                float2 f3 = __half22float2(hr[48 + c]);
                d0 += f0.x * av[2 * c]      + f0.y * av[2 * c + 1];
                d1 += f1.x * av[32 + 2 * c] + f1.y * av[32 + 2 * c + 1];
                d2 += f2.x * av[64 + 2 * c] + f2.y * av[64 + 2 * c + 1];
                d3 += f3.x * av[96 + 2 * c] + f3.y * av[96 + 2 * c + 1];
            }
            float* dst = half_ ? g_ar : g_al;
            *(float4*)&dst[row * 4] = make_float4(d0, d1, d2, d3);
            if (half_ == 0) {
                atomicMax(&smax[0], fenc(d0));
                atomicMax(&smax[1], fenc(d1));
                atomicMax(&smax[2], fenc(d2));
                atomicMax(&smax[3], fenc(d3));
            }
        }
    }
    __syncthreads();
    if (tid < 4) atomicMax(&g_gmaxenc[Lidx][tid], smax[tid]);
}

// ---------------- CSR build --------------------------------------------------
__global__ void zero_deg(int n) {
    int i = blockIdx.x * blockDim.x + threadIdx.x;
    if (i < n) g_deg[i] = 0;
}
__global__ void count_deg(const int* __restrict__ dst, int E) {
    int e = blockIdx.x * blockDim.x + threadIdx.x;
    if (e < E) atomicAdd(&g_deg[dst[e]], 1);
}
__global__ void scanA(int n) {
    __shared__ int sh[SCANB];
    int i = blockIdx.x * SCANB + threadIdx.x;
    int v = (i < n) ? g_deg[i] : 0;
    sh[threadIdx.x] = v;
    __syncthreads();
    for (int off = 1; off < SCANB; off <<= 1) {
        int t = (threadIdx.x >= off) ? sh[threadIdx.x - off] : 0;
        __syncthreads();
        sh[threadIdx.x] += t;
        __syncthreads();
    }
    if (i < n) g_rowptr[i] = sh[threadIdx.x] - v;
    if (threadIdx.x == SCANB - 1) g_bsum[blockIdx.x] = sh[SCANB - 1];
}
__global__ void scanB(int nb) {
    __shared__ int sh[256];
    int v = (threadIdx.x < nb) ? g_bsum[threadIdx.x] : 0;
    sh[threadIdx.x] = v;
    __syncthreads();
    for (int off = 1; off < 256; off <<= 1) {
        int t = (threadIdx.x >= off) ? sh[threadIdx.x - off] : 0;
        __syncthreads();
        sh[threadIdx.x] += t;
        __syncthreads();
    }
    if (threadIdx.x < nb) g_bsum[threadIdx.x] = sh[threadIdx.x] - v;
}
__global__ void scanC(int n, int E) {
    int i = blockIdx.x * blockDim.x + threadIdx.x;
    if (i < NG * DF) g_pool[i] = 0.f;
    if (i < NG) g_cnt[i] = 0;
    if (i < n) {
        int r = g_rowptr[i] + g_bsum[i / SCANB];
        g_rowptr[i] = r;
        g_pos[i] = r;
    }
    if (i == 0) g_rowptr[n] = E;
}
__global__ void csr_fill(const int* __restrict__ src, const int* __restrict__ dst, int E) {
    int e = blockIdx.x * blockDim.x + threadIdx.x;
    if (e >= E) return;
    int p = atomicAdd(&g_pos[dst[e]], 1);
    g_csr[p] = src[e];
}

// ---------------- fused per-node GAT: pair-gather (2 edges / warp-iter) -------
__global__ void gat_node(const float* __restrict__ bias, int n, int L, int last,
                         const int* __restrict__ batch, float* __restrict__ lastOut) {
    const unsigned FULL = 0xFFFFFFFFu;
    int wid = (blockIdx.x * blockDim.x + threadIdx.x) >> 5;
    int l = threadIdx.x & 31;
    if (wid >= n) return;
    int rp = g_rowptr[wid], re = g_rowptr[wid + 1];

    float4 ad = *(const float4*)&g_al[wid * 4];
    float4 bd = *(const float4*)&g_ar[wid * 4];

    int h  = l >> 3;          // exp-phase head
    int eo = l & 7;           // exp-phase edge slot
    int m  = l & 15;          // gather dims 8m..8m+8
    int g  = m >> 2;          // gather-phase head (dims' head)
    int half_ = l >> 4;       // 0: even edges, 1: odd edges

    float arh = sel4(bd, h);
    float mh  = lrelu(fdec(g_gmaxenc[L][h]) + arh);

    float zacc = 0.f;
    float acc[8];
#pragma unroll
    for (int j = 0; j < 8; j++) acc[j] = 0.f;

    for (int j0 = rp; j0 < re; j0 += 8) {
        int cnt = re - j0;
        int s_l = wid;
        float e_l = 0.f;
        if (eo < cnt) {
            s_l = g_csr[j0 + eo];
            float als = __ldg(&g_al[s_l * 4 + h]);
            e_l = __expf(lrelu(als + arh) - mh);
            zacc += e_l;
        }
#pragma unroll
        for (int k = 0; k < 8; k += 2) {
            int eidx = k + half_;
            int   s  = __shfl_sync(FULL, s_l, eidx);
            float ek = __shfl_sync(FULL, e_l, (g << 3) | eidx);
            if (eidx < cnt) {
                uint4 u = *(const uint4*)&g_XWh[s * 128 + 8 * m];
                float2 f0 = __half22float2(*(__half2*)&u.x);
                float2 f1 = __half22float2(*(__half2*)&u.y);
                float2 f2 = __half22float2(*(__half2*)&u.z);
                float2 f3 = __half22float2(*(__half2*)&u.w);
                acc[0] += ek * f0.x; acc[1] += ek * f0.y;
                acc[2] += ek * f1.x; acc[3] += ek * f1.y;
                acc[4] += ek * f2.x; acc[5] += ek * f2.y;
                acc[6] += ek * f3.x; acc[7] += ek * f3.y;
            }
        }
    }
    // z: reduce over the 8 edge slots within each head group
#pragma unroll
    for (int o = 1; o < 8; o <<= 1) zacc += __shfl_xor_sync(FULL, zacc, o);
    // combine even/odd edge halves of acc
#pragma unroll
    for (int j = 0; j < 8; j++) acc[j] += __shfl_xor_sync(FULL, acc[j], 16);

    // per-gather-head constants
    float z_g   = __shfl_sync(FULL, zacc, g << 3);
    float arh_g = sel4(bd, g);
    float mh_g  = lrelu(fdec(g_gmaxenc[L][g]) + arh_g);
    float slg_g = lrelu(sel4(ad, g) + arh_g);
    float eself = __expf(slg_g - mh_g);
    float rz    = 1.f / (z_g + eself);

    // self message (8 halfs at dims 8m)
    uint4 us = *(const uint4*)&g_XWh[wid * 128 + 8 * m];
    float2 s0 = __half22float2(*(__half2*)&us.x);
    float2 s1 = __half22float2(*(__half2*)&us.y);
    float2 s2 = __half22float2(*(__half2*)&us.z);
    float2 s3 = __half22float2(*(__half2*)&us.w);
    float sf[8] = { s0.x, s0.y, s1.x, s1.y, s2.x, s2.y, s3.x, s3.y };

    float4 b0 = *(const float4*)&bias[8 * m];
    float4 b1 = *(const float4*)&bias[8 * m + 4];
    float bf[8] = { b0.x, b0.y, b0.z, b0.w, b1.x, b1.y, b1.z, b1.w };

    float o[8];
#pragma unroll
    for (int j = 0; j < 8; j++)
        o[j] = fmaxf((acc[j] + eself * sf[j]) * rz + bf[j], 0.f);

    if (!last) {
        if (half_ == 0) {
            __half2 h0 = __floats2half2_rn(o[0], o[1]);
            __half2 h1 = __floats2half2_rn(o[2], o[3]);
            __half2 h2 = __floats2half2_rn(o[4], o[5]);
            __half2 h3 = __floats2half2_rn(o[6], o[7]);
            uint4 u;
            u.x = *(uint32_t*)&h0; u.y = *(uint32_t*)&h1;
            u.z = *(uint32_t*)&h2; u.w = *(uint32_t*)&h3;
            stcs4u(&g_Hh[wid * 128 + 8 * m], u);
        }
    } else {
        // lanes 0-15 write dims [8m,8m+4), lanes 16-31 write [8m+4,8m+8)
        float4 v = half_ ? make_float4(o[4], o[5], o[6], o[7])
                         : make_float4(o[0], o[1], o[2], o[3]);
        int off = wid * 128 + 8 * m + 4 * half_;
        stcs4(&lastOut[off], v);
        int b = batch[wid];
        redAdd4(&g_pool[b * 128 + 8 * m + 4 * half_], v);
        if (l == 0) atomicAdd(&g_cnt[b], 1);
    }
}

// ---------------- MLP head ----------------------------------------------------
__global__ void mlp_kernel(const float* __restrict__ lin1w, const float* __restrict__ lin1b,
                           const float* __restrict__ lin2w, const float* __restrict__ lin2b,
                           float* __restrict__ out) {
    __shared__ float pr[128];
    __shared__ float gg[128];
    __shared__ float lo[NCLS];
    int gr = blockIdx.x;
    int c = threadIdx.x;
    float cnt = (float)max(g_cnt[gr], 1);
    pr[c] = g_pool[gr * 128 + c] / cnt;
    __syncthreads();
    float acc = lin1b[c];
#pragma unroll 8
    for (int k = 0; k < 128; k++) acc += pr[k] * lin1w[k * 128 + c];
    gg[c] = fmaxf(acc, 0.f);
    __syncthreads();
    if (c < NCLS) {
        float a = lin2b[c];
#pragma unroll 8
        for (int k = 0; k < 128; k++) a += gg[k] * lin2w[k * NCLS + c];
        lo[c] = a;
    }
    __syncthreads();
    if (c == 0) {
        float mx = lo[0];
#pragma unroll
        for (int j = 1; j < NCLS; j++) mx = fmaxf(mx, lo[j]);
        float s = 0.f;
#pragma unroll
        for (int j = 0; j < NCLS; j++) s += expf(lo[j] - mx);
        float lse = mx + logf(s);
#pragma unroll
        for (int j = 0; j < NCLS; j++) out[gr * NCLS + j] = lo[j] - lse;
    }
}

// ---------------- host launcher ---------------------------------------------
extern "C" void kernel_launch(void* const* d_in, const int* in_sizes, int n_in,
                              void* d_out, int out_size) {
    const float* x    = (const float*)d_in[0];
    const int*   eidx = (const int*)d_in[1];
    const int*   batch= (const int*)d_in[2];
    const float* W[3]  = { (const float*)d_in[3], (const float*)d_in[7],  (const float*)d_in[11] };
    const float* al[3] = { (const float*)d_in[4], (const float*)d_in[8],  (const float*)d_in[12] };
    const float* ar[3] = { (const float*)d_in[5], (const float*)d_in[9],  (const float*)d_in[13] };
    const float* bb[3] = { (const float*)d_in[6], (const float*)d_in[10], (const float*)d_in[14] };
    const float* lin1w = (const float*)d_in[15];
    const float* lin1b = (const float*)d_in[16];
    const float* lin2w = (const float*)d_in[17];
    const float* lin2b = (const float*)d_in[18];

    int n = in_sizes[0] / DF;
    int E = in_sizes[1] / 2;
    const int* src = eidx;
    const int* dst = eidx + E;

    float* out_logits = (float*)d_out;
    float* out_last   = (float*)d_out + NG * NCLS;

    __half* hh; cudaGetSymbolAddress((void**)&hh, g_Hh);
    uint4* wf; cudaGetSymbolAddress((void**)&wf, g_WfT);

    static int inited = 0;
    static cudaStream_t sB;
    static cudaEvent_t evF, evJ;
    if (!inited) {
        cudaFuncSetAttribute(gemm_mma, cudaFuncAttributeMaxDynamicSharedMemorySize, GS_TOT);
        cudaStreamCreateWithFlags(&sB, cudaStreamNonBlocking);
        cudaEventCreateWithFlags(&evF, cudaEventDisableTiming);
        cudaEventCreateWithFlags(&evJ, cudaEventDisableTiming);
        inited = 1;
    }

    int warpNB = (n * 32 + 255) / 256;
    int edgeTB = (E + 255) / 256;
    int nodeTB = (n + 255) / 256;
    int nScanB = (n + SCANB - 1) / SCANB;
    int gemmB  = (n + 63) / 64;

    prep_all<<<24, 256>>>(W[0], W[1], W[2]);                              // 0
    cudaEventRecord(evF, 0);
    cudaStreamWaitEvent(sB, evF, 0);
    zero_deg<<<nodeTB, 256, 0, sB>>>(n);                                  // 1
    count_deg<<<edgeTB, 256, 0, sB>>>(dst, E);                            // 2
    gemm_mma<<<gemmB, 256, GS_TOT>>>(x, 0, wf, al[0], ar[0], n, 0);       // 3 <- profiled
    scanA<<<nScanB, SCANB, 0, sB>>>(n);                                   // 4
    scanB<<<1, 256, 0, sB>>>(nScanB);                                     // 5
    scanC<<<nodeTB, 256, 0, sB>>>(n, E);                                  // 6
    csr_fill<<<edgeTB, 256, 0, sB>>>(src, dst, E);                        // 7

    cudaEventRecord(evJ, sB);
    cudaStreamWaitEvent(0, evJ, 0);

    gat_node<<<warpNB, 256>>>(bb[0], n, 0, 0, batch, out_last);
    for (int L = 1; L < 3; L++) {
        gemm_mma<<<gemmB, 256, GS_TOT>>>(hh, 1, wf + L * 2048, al[L], ar[L], n, L);
        gat_node<<<warpNB, 256>>>(bb[L], n, L, (L == 2) ? 1 : 0, batch, out_last);
    }

    mlp_kernel<<<NG, 128>>>(lin1w, lin1b, lin2w, lin2b, out_logits);
}

// round 14
// speedup vs baseline: 1.1631x; 1.1631x over previous
#include <cuda_runtime.h>
#include <cuda_bf16.h>
#include <cuda_fp16.h>
#include <cstdint>
#include <math.h>

#define NND 100000
#define NE  1600000
#define DF  128
#define HEADS 4
#define NG  64
#define NCLS 10
#define NEG 0.2f
#define SCANB 512

// ---------------- scratch ----------------------------------------------------
__device__ __align__(16) __half g_XWh[NND * DF];   // fp16 x@W (messages+self)
__device__ __align__(16) __half g_Hh [NND * DF];   // fp16 relu(layer output)
__device__ __align__(16) float  g_al[NND * HEADS];
__device__ __align__(16) float  g_ar[NND * HEADS];
__device__ unsigned g_gmaxenc[3][HEADS];
__device__ int   g_deg[NND];
__device__ int   g_rowptr[NND + 1];
__device__ int   g_pos[NND];
__device__ int   g_bsum[(NND + SCANB - 1) / SCANB];
__device__ int   g_csr[NE];
__device__ float g_pool[NG * DF];
__device__ int   g_cnt[NG];
__device__ __align__(16) uint4 g_WfT[3][2048];     // fp16 W^T swizzled

// ---------------- helpers ----------------------------------------------------
__device__ __forceinline__ float lrelu(float x) { return x > 0.f ? x : NEG * x; }
__device__ __forceinline__ unsigned fenc(float f) {
    unsigned u = __float_as_uint(f);
    return (u & 0x80000000u) ? ~u : (u | 0x80000000u);
}
__device__ __forceinline__ float fdec(unsigned u) {
    return (u & 0x80000000u) ? __uint_as_float(u & 0x7FFFFFFFu)
                             : __uint_as_float(~u);
}
__device__ __forceinline__ float sel4(float4 v, int h) {
    return h == 0 ? v.x : h == 1 ? v.y : h == 2 ? v.z : v.w;
}
__device__ __forceinline__ void redAdd4(float* p, float4 v) {
    asm volatile("red.global.add.v4.f32 [%0], {%1,%2,%3,%4};"
                 :: "l"(p), "f"(v.x), "f"(v.y), "f"(v.z), "f"(v.w) : "memory");
}
__device__ __forceinline__ void stcs4(float* p, float4 v) {
    asm volatile("st.global.cs.v4.f32 [%0], {%1,%2,%3,%4};"
                 :: "l"(p), "f"(v.x), "f"(v.y), "f"(v.z), "f"(v.w) : "memory");
}
__device__ __forceinline__ void stcs2u(void* p, uint2 u) {
    asm volatile("st.global.cs.v2.u32 [%0], {%1,%2};"
                 :: "l"(p), "r"(u.x), "r"(u.y) : "memory");
}
__device__ __forceinline__ uint32_t smem_u32(const void* p) {
    uint32_t a;
    asm("{ .reg .u64 t; cvta.to.shared.u64 t, %1; cvt.u32.u64 %0, t; }" : "=r"(a) : "l"(p));
    return a;
}
__device__ __forceinline__ void ldm4(uint32_t& r0, uint32_t& r1, uint32_t& r2,
                                     uint32_t& r3, uint32_t addr) {
    asm volatile("ldmatrix.sync.aligned.m8n8.x4.shared.b16 {%0,%1,%2,%3}, [%4];"
                 : "=r"(r0), "=r"(r1), "=r"(r2), "=r"(r3) : "r"(addr));
}
__device__ __forceinline__ void mma16816f(float* d, uint32_t a0, uint32_t a1,
                                          uint32_t a2, uint32_t a3,
                                          uint32_t b0, uint32_t b1) {
    asm volatile(
        "mma.sync.aligned.m16n8k16.row.col.f32.f16.f16.f32 "
        "{%0,%1,%2,%3}, {%4,%5,%6,%7}, {%8,%9}, {%0,%1,%2,%3};"
        : "+f"(d[0]), "+f"(d[1]), "+f"(d[2]), "+f"(d[3])
        : "r"(a0), "r"(a1), "r"(a2), "r"(a3), "r"(b0), "r"(b1));
}

union H16x8 { __half h[8]; uint4 u; };

// ---------------- weight prep + gmax zero (all layers, one launch) ------------
__global__ void prep_all(const float* __restrict__ W0, const float* __restrict__ W1,
                         const float* __restrict__ W2) {
    if (blockIdx.x == 0 && threadIdx.x < 12)
        ((unsigned*)g_gmaxenc)[threadIdx.x] = 0u;
    int L = blockIdx.x >> 3;
    int i = (blockIdx.x & 7) * 256 + threadIdx.x;
    const float* W = (L == 0) ? W0 : (L == 1) ? W1 : W2;
    int nn = i >> 4, c = i & 15;
    H16x8 F;
#pragma unroll
    for (int j = 0; j < 8; j++)
        F.h[j] = __float2half(W[(c * 8 + j) * 128 + nn]);
    g_WfT[L][nn * 16 + (c ^ (nn & 7))] = F.u;
}

// ---------------- fp16 HMMA GEMM + fused al/ar + almax -----------------------
#define GS_A   0
#define GS_W   16384
#define GS_ATT 49152
#define GS_TOT 50176
#define HS_STRIDE 136

__global__ void __launch_bounds__(256, 3) gemm_mma(
    const void* __restrict__ Ain, int aHalf, const uint4* __restrict__ WfT,
    const float* __restrict__ attl, const float* __restrict__ attr,
    int n, int Lidx) {
    extern __shared__ char smem[];
    __shared__ unsigned smax[4];
    uint32_t sb = smem_u32(smem);
    int tid = threadIdx.x, w = tid >> 5, l = tid & 31;
    int rg = w & 3, ch = w >> 2;
    int row0 = blockIdx.x * 64;

    {
        uint4* wf = (uint4*)(smem + GS_W);
        for (int i = tid; i < 2048; i += 256) wf[i] = WfT[i];
    }
    if (aHalf) {
        const __half* Ah = (const __half*)Ain;
        for (int i = tid; i < 1024; i += 256) {
            int r = i >> 4, c = i & 15;
            int row = row0 + r;
            uint4 u = make_uint4(0u, 0u, 0u, 0u);
            if (row < n) u = __ldcs((const uint4*)&Ah[row * 128 + c * 8]);
            *(uint4*)(smem + GS_A + r * 256 + ((c ^ (r & 7)) << 4)) = u;
        }
    } else {
        const float* A = (const float*)Ain;
        for (int i = tid; i < 1024; i += 256) {
            int r = i >> 4, c = i & 15;
            int row = row0 + r;
            float4 v0 = make_float4(0.f, 0.f, 0.f, 0.f), v1 = v0;
            if (row < n) {
                v0 = __ldcs((const float4*)&A[row * 128 + c * 8]);
                v1 = __ldcs((const float4*)&A[row * 128 + c * 8 + 4]);
            }
            H16x8 F;
            F.h[0] = __float2half(v0.x); F.h[1] = __float2half(v0.y);
            F.h[2] = __float2half(v0.z); F.h[3] = __float2half(v0.w);
            F.h[4] = __float2half(v1.x); F.h[5] = __float2half(v1.y);
            F.h[6] = __float2half(v1.z); F.h[7] = __float2half(v1.w);
            *(uint4*)(smem + GS_A + r * 256 + ((c ^ (r & 7)) << 4)) = F.u;
        }
    }
    __syncthreads();

    int aRow = rg * 16 + ((l >> 3) & 1) * 8 + (l & 7);
    int aChk = (l >> 4) & 1;
    uint32_t aBase = sb + GS_A + aRow * 256;
    int aXor = aRow & 7;
    int bRowL = ((l >> 4) & 1) * 8 + (l & 7);
    int bChk = (l >> 3) & 1;

    float acc[32];
#pragma unroll
    for (int i = 0; i < 32; i++) acc[i] = 0.f;

#pragma unroll
    for (int ks = 0; ks < 8; ks++) {
        uint32_t a0, a1, a2, a3;
        ldm4(a0, a1, a2, a3, aBase + (((2 * ks + aChk) ^ aXor) << 4));
#pragma unroll
        for (int p = 0; p < 4; p++) {
            int bRow = ch * 64 + p * 16 + bRowL;
            uint32_t bAddr = sb + GS_W + bRow * 256
                           + (((2 * ks + bChk) ^ (bRow & 7)) << 4);
            uint32_t b0, b1, b2, b3;
            ldm4(b0, b1, b2, b3, bAddr);
            mma16816f(&acc[(2 * p) * 4],     a0, a1, a2, a3, b0, b1);
            mma16816f(&acc[(2 * p + 1) * 4], a0, a1, a2, a3, b2, b3);
        }
    }
    __syncthreads();

    __half* Hs = (__half*)smem;
    float* att = (float*)(smem + GS_ATT);
    att[tid] = (tid < 128) ? attl[tid] : attr[tid - 128];
    if (tid < 4) smax[tid] = 0u;
    {
        int r1 = rg * 16 + (l >> 2);
#pragma unroll
        for (int nt = 0; nt < 8; nt++) {
            int p = nt >> 1, t = nt & 1;
            int col = ch * 64 + p * 16 + t * 8 + (l & 3) * 2;
            float* d = &acc[nt * 4];
            __half2 lo = __floats2half2_rn(d[0], d[1]);
            __half2 hi = __floats2half2_rn(d[2], d[3]);
            *(__half2*)&Hs[r1 * HS_STRIDE + col]       = lo;
            *(__half2*)&Hs[(r1 + 8) * HS_STRIDE + col] = hi;
        }
    }
    __syncthreads();

    for (int i = tid; i < 1024; i += 256) {
        int r = i >> 4, c = i & 15;
        int row = row0 + r;
        if (row < n)
            *(uint4*)&g_XWh[row * 128 + c * 8] =
                *(uint4*)&Hs[r * HS_STRIDE + c * 8];
    }
    if (tid < 128) {
        int half_ = tid >> 6;
        int r = tid & 63;
        int row = row0 + r;
        if (row < n) {
            const float* av = att + half_ * 128;
            const __half2* hr = (const __half2*)&Hs[r * HS_STRIDE];
            float d0 = 0.f, d1 = 0.f, d2 = 0.f, d3 = 0.f;
#pragma unroll 8
            for (int c = 0; c < 16; c++) {
                float2 f0 = __half22float2(hr[c]);
                float2 f1 = __half22float2(hr[16 + c]);
                float2 f2 = __half22float2(hr[32 + c]);
                float2 f3 = __half22float2(hr[48 + c]);
                d0 += f0.x * av[2 * c]      + f0.y * av[2 * c + 1];
                d1 += f1.x * av[32 + 2 * c] + f1.y * av[32 + 2 * c + 1];
                d2 += f2.x * av[64 + 2 * c] + f2.y * av[64 + 2 * c + 1];
                d3 += f3.x * av[96 + 2 * c] + f3.y * av[96 + 2 * c + 1];
            }
            float* dst = half_ ? g_ar : g_al;
            *(float4*)&dst[row * 4] = make_float4(d0, d1, d2, d3);
            if (half_ == 0) {
                atomicMax(&smax[0], fenc(d0));
                atomicMax(&smax[1], fenc(d1));
                atomicMax(&smax[2], fenc(d2));
                atomicMax(&smax[3], fenc(d3));
            }
        }
    }
    __syncthreads();
    if (tid < 4) atomicMax(&g_gmaxenc[Lidx][tid], smax[tid]);
}

// ---------------- CSR build --------------------------------------------------
__global__ void zero_deg(int n) {
    int i = blockIdx.x * blockDim.x + threadIdx.x;
    if (i < n) g_deg[i] = 0;
}
__global__ void count_deg(const int* __restrict__ dst, int E) {
    int e = blockIdx.x * blockDim.x + threadIdx.x;
    if (e < E) atomicAdd(&g_deg[dst[e]], 1);
}
__global__ void scanA(int n) {
    __shared__ int sh[SCANB];
    int i = blockIdx.x * SCANB + threadIdx.x;
    int v = (i < n) ? g_deg[i] : 0;
    sh[threadIdx.x] = v;
    __syncthreads();
    for (int off = 1; off < SCANB; off <<= 1) {
        int t = (threadIdx.x >= off) ? sh[threadIdx.x - off] : 0;
        __syncthreads();
        sh[threadIdx.x] += t;
        __syncthreads();
    }
    if (i < n) g_rowptr[i] = sh[threadIdx.x] - v;
    if (threadIdx.x == SCANB - 1) g_bsum[blockIdx.x] = sh[SCANB - 1];
}
__global__ void scanB(int nb) {
    __shared__ int sh[256];
    int v = (threadIdx.x < nb) ? g_bsum[threadIdx.x] : 0;
    sh[threadIdx.x] = v;
    __syncthreads();
    for (int off = 1; off < 256; off <<= 1) {
        int t = (threadIdx.x >= off) ? sh[threadIdx.x - off] : 0;
        __syncthreads();
        sh[threadIdx.x] += t;
        __syncthreads();
    }
    if (threadIdx.x < nb) g_bsum[threadIdx.x] = sh[threadIdx.x] - v;
}
__global__ void scanC(int n, int E) {
    int i = blockIdx.x * blockDim.x + threadIdx.x;
    if (i < NG * DF) g_pool[i] = 0.f;
    if (i < NG) g_cnt[i] = 0;
    if (i < n) {
        int r = g_rowptr[i] + g_bsum[i / SCANB];
        g_rowptr[i] = r;
        g_pos[i] = r;
    }
    if (i == 0) g_rowptr[n] = E;
}
__global__ void csr_fill(const int* __restrict__ src, const int* __restrict__ dst, int E) {
    int e = blockIdx.x * blockDim.x + threadIdx.x;
    if (e >= E) return;
    int p = atomicAdd(&g_pos[dst[e]], 1);
    g_csr[p] = src[e];
}

// ---------------- fused per-node GAT (R12 body, 128-thr blocks) ---------------
__global__ void gat_node(const float* __restrict__ bias, int n, int L, int last,
                         const int* __restrict__ batch, float* __restrict__ lastOut) {
    int wid = (blockIdx.x * blockDim.x + threadIdx.x) >> 5;
    int l = threadIdx.x & 31;
    if (wid >= n) return;
    int rp = g_rowptr[wid], re = g_rowptr[wid + 1];

    float4 ad = *(const float4*)&g_al[wid * 4];
    float4 bd = *(const float4*)&g_ar[wid * 4];

    int h = l >> 3;
    int eo = l & 7;
    float arh  = sel4(bd, h);
    float mh   = lrelu(fdec(g_gmaxenc[L][h]) + arh);
    float slgh = lrelu(sel4(ad, h) + arh);

    float zacc = 0.f;
    float4 acc = make_float4(0.f, 0.f, 0.f, 0.f);

    int s_cur = wid; float als_cur = 0.f;
    if (rp + eo < re) {
        s_cur = g_csr[rp + eo];
        als_cur = __ldg(&g_al[s_cur * 4 + h]);
    }
    for (int j0 = rp; j0 < re; j0 += 8) {
        int s_nxt = wid; float als_nxt = 0.f;
        if (j0 + 8 + eo < re) {
            s_nxt = g_csr[j0 + 8 + eo];
            als_nxt = __ldg(&g_al[s_nxt * 4 + h]);
        }
        float e_l = 0.f;
        if (j0 + eo < re) {
            e_l = __expf(lrelu(als_cur + arh) - mh);
            zacc += e_l;
        }
        int kmax = min(8, re - j0);
#pragma unroll 8
        for (int k = 0; k < kmax; k++) {
            int s = __shfl_sync(0xFFFFFFFFu, s_cur, k);
            float ek = __shfl_sync(0xFFFFFFFFu, e_l, (l & 24) | k);
            uint2 u = *(const uint2*)&g_XWh[s * 128 + 4 * l];
            __half2 p0 = *(__half2*)&u.x, p1 = *(__half2*)&u.y;
            float2 f0 = __half22float2(p0), f1 = __half22float2(p1);
            acc.x += ek * f0.x; acc.y += ek * f0.y;
            acc.z += ek * f1.x; acc.w += ek * f1.y;
        }
        s_cur = s_nxt; als_cur = als_nxt;
    }
#pragma unroll
    for (int o = 1; o < 8; o <<= 1) zacc += __shfl_xor_sync(0xFFFFFFFFu, zacc, o);

    float eself = __expf(slgh - mh);
    float rz = 1.f / (zacc + eself);
    uint2 us = *(const uint2*)&g_XWh[wid * 128 + 4 * l];
    __half2 s0 = *(__half2*)&us.x, s1 = *(__half2*)&us.y;
    float2 fs0 = __half22float2(s0), fs1 = __half22float2(s1);
    float4 bv = *(const float4*)&bias[4 * l];
    float4 o;
    o.x = fmaxf((acc.x + eself * fs0.x) * rz + bv.x, 0.f);
    o.y = fmaxf((acc.y + eself * fs0.y) * rz + bv.y, 0.f);
    o.z = fmaxf((acc.z + eself * fs1.x) * rz + bv.z, 0.f);
    o.w = fmaxf((acc.w + eself * fs1.y) * rz + bv.w, 0.f);

    if (!last) {
        __half2 h0 = __floats2half2_rn(o.x, o.y);
        __half2 h1 = __floats2half2_rn(o.z, o.w);
        uint2 u;
        u.x = *(uint32_t*)&h0; u.y = *(uint32_t*)&h1;
        stcs2u(&g_Hh[wid * 128 + 4 * l], u);
    } else {
        stcs4(&lastOut[wid * 128 + 4 * l], o);
        int b = batch[wid];
        redAdd4(&g_pool[b * 128 + 4 * l], o);
        if (l == 0) atomicAdd(&g_cnt[b], 1);
    }
}

// ---------------- MLP head ----------------------------------------------------
__global__ void mlp_kernel(const float* __restrict__ lin1w, const float* __restrict__ lin1b,
                           const float* __restrict__ lin2w, const float* __restrict__ lin2b,
                           float* __restrict__ out) {
    __shared__ float pr[128];
    __shared__ float gg[128];
    __shared__ float lo[NCLS];
    int gr = blockIdx.x;
    int c = threadIdx.x;
    float cnt = (float)max(g_cnt[gr], 1);
    pr[c] = g_pool[gr * 128 + c] / cnt;
    __syncthreads();
    float acc = lin1b[c];
#pragma unroll 8
    for (int k = 0; k < 128; k++) acc += pr[k] * lin1w[k * 128 + c];
    gg[c] = fmaxf(acc, 0.f);
    __syncthreads();
    if (c < NCLS) {
        float a = lin2b[c];
#pragma unroll 8
        for (int k = 0; k < 128; k++) a += gg[k] * lin2w[k * NCLS + c];
        lo[c] = a;
    }
    __syncthreads();
    if (c == 0) {
        float mx = lo[0];
#pragma unroll
        for (int j = 1; j < NCLS; j++) mx = fmaxf(mx, lo[j]);
        float s = 0.f;
#pragma unroll
        for (int j = 0; j < NCLS; j++) s += expf(lo[j] - mx);
        float lse = mx + logf(s);
#pragma unroll
        for (int j = 0; j < NCLS; j++) out[gr * NCLS + j] = lo[j] - lse;
    }
}

// ---------------- host launcher ---------------------------------------------
extern "C" void kernel_launch(void* const* d_in, const int* in_sizes, int n_in,
                              void* d_out, int out_size) {
    const float* x    = (const float*)d_in[0];
    const int*   eidx = (const int*)d_in[1];
    const int*   batch= (const int*)d_in[2];
    const float* W[3]  = { (const float*)d_in[3], (const float*)d_in[7],  (const float*)d_in[11] };
    const float* al[3] = { (const float*)d_in[4], (const float*)d_in[8],  (const float*)d_in[12] };
    const float* ar[3] = { (const float*)d_in[5], (const float*)d_in[9],  (const float*)d_in[13] };
    const float* bb[3] = { (const float*)d_in[6], (const float*)d_in[10], (const float*)d_in[14] };
    const float* lin1w = (const float*)d_in[15];
    const float* lin1b = (const float*)d_in[16];
    const float* lin2w = (const float*)d_in[17];
    const float* lin2b = (const float*)d_in[18];

    int n = in_sizes[0] / DF;
    int E = in_sizes[1] / 2;
    const int* src = eidx;
    const int* dst = eidx + E;

    float* out_logits = (float*)d_out;
    float* out_last   = (float*)d_out + NG * NCLS;

    __half* hh; cudaGetSymbolAddress((void**)&hh, g_Hh);
    uint4* wf; cudaGetSymbolAddress((void**)&wf, g_WfT);

    static int inited = 0;
    static cudaStream_t sB;
    static cudaEvent_t evF, evJ;
    if (!inited) {
        cudaFuncSetAttribute(gemm_mma, cudaFuncAttributeMaxDynamicSharedMemorySize, GS_TOT);
        cudaStreamCreateWithFlags(&sB, cudaStreamNonBlocking);
        cudaEventCreateWithFlags(&evF, cudaEventDisableTiming);
        cudaEventCreateWithFlags(&evJ, cudaEventDisableTiming);
        inited = 1;
    }

    int gatB   = (n * 32 + 127) / 128;   // 128-thr blocks for finer tail balance
    int edgeTB = (E + 255) / 256;
    int nodeTB = (n + 255) / 256;
    int nScanB = (n + SCANB - 1) / SCANB;
    int gemmB  = (n + 63) / 64;

    prep_all<<<24, 256>>>(W[0], W[1], W[2]);                              // 0
    cudaEventRecord(evF, 0);
    cudaStreamWaitEvent(sB, evF, 0);
    zero_deg<<<nodeTB, 256, 0, sB>>>(n);                                  // 1
    count_deg<<<edgeTB, 256, 0, sB>>>(dst, E);                            // 2
    gemm_mma<<<gemmB, 256, GS_TOT>>>(x, 0, wf, al[0], ar[0], n, 0);       // 3 <- profiled
    scanA<<<nScanB, SCANB, 0, sB>>>(n);                                   // 4
    scanB<<<1, 256, 0, sB>>>(nScanB);                                     // 5
    scanC<<<nodeTB, 256, 0, sB>>>(n, E);                                  // 6
    csr_fill<<<edgeTB, 256, 0, sB>>>(src, dst, E);                        // 7

    cudaEventRecord(evJ, sB);
    cudaStreamWaitEvent(0, evJ, 0);

    gat_node<<<gatB, 128>>>(bb[0], n, 0, 0, batch, out_last);
    for (int L = 1; L < 3; L++) {
        gemm_mma<<<gemmB, 256, GS_TOT>>>(hh, 1, wf + L * 2048, al[L], ar[L], n, L);
        gat_node<<<gatB, 128>>>(bb[L], n, L, (L == 2) ? 1 : 0, batch, out_last);
    }

    mlp_kernel<<<NG, 128>>>(lin1w, lin1b, lin2w, lin2b, out_logits);
}

// round 15
// speedup vs baseline: 1.1823x; 1.0165x over previous
#include <cuda_runtime.h>
#include <cuda_bf16.h>
#include <cuda_fp16.h>
#include <cstdint>
#include <math.h>

#define NND 100000
#define NE  1600000
#define DF  128
#define HEADS 4
#define NG  64
#define NCLS 10
#define NEG 0.2f
#define SCANB 512

// ---------------- scratch ----------------------------------------------------
__device__ __align__(16) __half g_XWh[NND * DF];   // fp16 x@W (messages+self)
__device__ __align__(16) __half g_Hh [NND * DF];   // fp16 relu(layer output)
__device__ __align__(16) float  g_al[NND * HEADS];
__device__ __align__(16) float  g_ar[NND * HEADS];
__device__ unsigned g_gmaxenc[3][HEADS];
__device__ int   g_deg[NND];
__device__ int   g_rowptr[NND + 1];
__device__ int   g_pos[NND];
__device__ int   g_bsum[(NND + SCANB - 1) / SCANB];
__device__ int   g_csr[NE];
__device__ float g_pool[NG * DF];
__device__ int   g_cnt[NG];
__device__ __align__(16) uint4 g_WfT[3][2048];     // fp16 W^T swizzled

// ---------------- helpers ----------------------------------------------------
__device__ __forceinline__ float lrelu(float x) { return x > 0.f ? x : NEG * x; }
__device__ __forceinline__ unsigned fenc(float f) {
    unsigned u = __float_as_uint(f);
    return (u & 0x80000000u) ? ~u : (u | 0x80000000u);
}
__device__ __forceinline__ float fdec(unsigned u) {
    return (u & 0x80000000u) ? __uint_as_float(u & 0x7FFFFFFFu)
                             : __uint_as_float(~u);
}
__device__ __forceinline__ float sel4(float4 v, int h) {
    return h == 0 ? v.x : h == 1 ? v.y : h == 2 ? v.z : v.w;
}
__device__ __forceinline__ void redAdd4(float* p, float4 v) {
    asm volatile("red.global.add.v4.f32 [%0], {%1,%2,%3,%4};"
                 :: "l"(p), "f"(v.x), "f"(v.y), "f"(v.z), "f"(v.w) : "memory");
}
__device__ __forceinline__ void stcs4(float* p, float4 v) {
    asm volatile("st.global.cs.v4.f32 [%0], {%1,%2,%3,%4};"
                 :: "l"(p), "f"(v.x), "f"(v.y), "f"(v.z), "f"(v.w) : "memory");
}
__device__ __forceinline__ void stcs2u(void* p, uint2 u) {
    asm volatile("st.global.cs.v2.u32 [%0], {%1,%2};"
                 :: "l"(p), "r"(u.x), "r"(u.y) : "memory");
}
__device__ __forceinline__ uint32_t smem_u32(const void* p) {
    uint32_t a;
    asm("{ .reg .u64 t; cvta.to.shared.u64 t, %1; cvt.u32.u64 %0, t; }" : "=r"(a) : "l"(p));
    return a;
}
__device__ __forceinline__ void ldm4(uint32_t& r0, uint32_t& r1, uint32_t& r2,
                                     uint32_t& r3, uint32_t addr) {
    asm volatile("ldmatrix.sync.aligned.m8n8.x4.shared.b16 {%0,%1,%2,%3}, [%4];"
                 : "=r"(r0), "=r"(r1), "=r"(r2), "=r"(r3) : "r"(addr));
}
__device__ __forceinline__ void mma16816f(float* d, uint32_t a0, uint32_t a1,
                                          uint32_t a2, uint32_t a3,
                                          uint32_t b0, uint32_t b1) {
    asm volatile(
        "mma.sync.aligned.m16n8k16.row.col.f32.f16.f16.f32 "
        "{%0,%1,%2,%3}, {%4,%5,%6,%7}, {%8,%9}, {%0,%1,%2,%3};"
        : "+f"(d[0]), "+f"(d[1]), "+f"(d[2]), "+f"(d[3])
        : "r"(a0), "r"(a1), "r"(a2), "r"(a3), "r"(b0), "r"(b1));
}

union H16x8 { __half h[8]; uint4 u; };

// ---------------- weight prep + gmax zero (all layers, one launch) ------------
__global__ void prep_all(const float* __restrict__ W0, const float* __restrict__ W1,
                         const float* __restrict__ W2) {
    if (blockIdx.x == 0 && threadIdx.x < 12)
        ((unsigned*)g_gmaxenc)[threadIdx.x] = 0u;
    int L = blockIdx.x >> 3;
    int i = (blockIdx.x & 7) * 256 + threadIdx.x;
    const float* W = (L == 0) ? W0 : (L == 1) ? W1 : W2;
    int nn = i >> 4, c = i & 15;
    H16x8 F;
#pragma unroll
    for (int j = 0; j < 8; j++)
        F.h[j] = __float2half(W[(c * 8 + j) * 128 + nn]);
    g_WfT[L][nn * 16 + (c ^ (nn & 7))] = F.u;
}

// ---------------- fp16 HMMA GEMM + fused al/ar + almax -----------------------
#define GS_A   0
#define GS_W   16384
#define GS_ATT 49152
#define GS_TOT 50176
#define HS_STRIDE 136

__global__ void __launch_bounds__(256, 3) gemm_mma(
    const void* __restrict__ Ain, int aHalf, const uint4* __restrict__ WfT,
    const float* __restrict__ attl, const float* __restrict__ attr,
    int n, int Lidx) {
    extern __shared__ char smem[];
    __shared__ unsigned smax[4];
    uint32_t sb = smem_u32(smem);
    int tid = threadIdx.x, w = tid >> 5, l = tid & 31;
    int rg = w & 3, ch = w >> 2;
    int row0 = blockIdx.x * 64;

    {
        uint4* wf = (uint4*)(smem + GS_W);
        for (int i = tid; i < 2048; i += 256) wf[i] = WfT[i];
    }
    if (aHalf) {
        const __half* Ah = (const __half*)Ain;
        for (int i = tid; i < 1024; i += 256) {
            int r = i >> 4, c = i & 15;
            int row = row0 + r;
            uint4 u = make_uint4(0u, 0u, 0u, 0u);
            if (row < n) u = __ldcs((const uint4*)&Ah[row * 128 + c * 8]);
            *(uint4*)(smem + GS_A + r * 256 + ((c ^ (r & 7)) << 4)) = u;
        }
    } else {
        const float* A = (const float*)Ain;
        for (int i = tid; i < 1024; i += 256) {
            int r = i >> 4, c = i & 15;
            int row = row0 + r;
            float4 v0 = make_float4(0.f, 0.f, 0.f, 0.f), v1 = v0;
            if (row < n) {
                v0 = __ldcs((const float4*)&A[row * 128 + c * 8]);
                v1 = __ldcs((const float4*)&A[row * 128 + c * 8 + 4]);
            }
            H16x8 F;
            F.h[0] = __float2half(v0.x); F.h[1] = __float2half(v0.y);
            F.h[2] = __float2half(v0.z); F.h[3] = __float2half(v0.w);
            F.h[4] = __float2half(v1.x); F.h[5] = __float2half(v1.y);
            F.h[6] = __float2half(v1.z); F.h[7] = __float2half(v1.w);
            *(uint4*)(smem + GS_A + r * 256 + ((c ^ (r & 7)) << 4)) = F.u;
        }
    }
    __syncthreads();

    int aRow = rg * 16 + ((l >> 3) & 1) * 8 + (l & 7);
    int aChk = (l >> 4) & 1;
    uint32_t aBase = sb + GS_A + aRow * 256;
    int aXor = aRow & 7;
    int bRowL = ((l >> 4) & 1) * 8 + (l & 7);
    int bChk = (l >> 3) & 1;

    float acc[32];
#pragma unroll
    for (int i = 0; i < 32; i++) acc[i] = 0.f;

#pragma unroll
    for (int ks = 0; ks < 8; ks++) {
        uint32_t a0, a1, a2, a3;
        ldm4(a0, a1, a2, a3, aBase + (((2 * ks + aChk) ^ aXor) << 4));
#pragma unroll
        for (int p = 0; p < 4; p++) {
            int bRow = ch * 64 + p * 16 + bRowL;
            uint32_t bAddr = sb + GS_W + bRow * 256
                           + (((2 * ks + bChk) ^ (bRow & 7)) << 4);
            uint32_t b0, b1, b2, b3;
            ldm4(b0, b1, b2, b3, bAddr);
            mma16816f(&acc[(2 * p) * 4],     a0, a1, a2, a3, b0, b1);
            mma16816f(&acc[(2 * p + 1) * 4], a0, a1, a2, a3, b2, b3);
        }
    }
    __syncthreads();

    __half* Hs = (__half*)smem;
    float* att = (float*)(smem + GS_ATT);
    att[tid] = (tid < 128) ? attl[tid] : attr[tid - 128];
    if (tid < 4) smax[tid] = 0u;
    {
        int r1 = rg * 16 + (l >> 2);
#pragma unroll
        for (int nt = 0; nt < 8; nt++) {
            int p = nt >> 1, t = nt & 1;
            int col = ch * 64 + p * 16 + t * 8 + (l & 3) * 2;
            float* d = &acc[nt * 4];
            __half2 lo = __floats2half2_rn(d[0], d[1]);
            __half2 hi = __floats2half2_rn(d[2], d[3]);
            *(__half2*)&Hs[r1 * HS_STRIDE + col]       = lo;
            *(__half2*)&Hs[(r1 + 8) * HS_STRIDE + col] = hi;
        }
    }
    __syncthreads();

    for (int i = tid; i < 1024; i += 256) {
        int r = i >> 4, c = i & 15;
        int row = row0 + r;
        if (row < n)
            *(uint4*)&g_XWh[row * 128 + c * 8] =
                *(uint4*)&Hs[r * HS_STRIDE + c * 8];
    }
    if (tid < 128) {
        int half_ = tid >> 6;
        int r = tid & 63;
        int row = row0 + r;
        if (row < n) {
            const float* av = att + half_ * 128;
            const __half2* hr = (const __half2*)&Hs[r * HS_STRIDE];
            float d0 = 0.f, d1 = 0.f, d2 = 0.f, d3 = 0.f;
#pragma unroll 8
            for (int c = 0; c < 16; c++) {
                float2 f0 = __half22float2(hr[c]);
                float2 f1 = __half22float2(hr[16 + c]);
                float2 f2 = __half22float2(hr[32 + c]);
                float2 f3 = __half22float2(hr[48 + c]);
                d0 += f0.x * av[2 * c]      + f0.y * av[2 * c + 1];
                d1 += f1.x * av[32 + 2 * c] + f1.y * av[32 + 2 * c + 1];
                d2 += f2.x * av[64 + 2 * c] + f2.y * av[64 + 2 * c + 1];
                d3 += f3.x * av[96 + 2 * c] + f3.y * av[96 + 2 * c + 1];
            }
            float* dst = half_ ? g_ar : g_al;
            *(float4*)&dst[row * 4] = make_float4(d0, d1, d2, d3);
            if (half_ == 0) {
                atomicMax(&smax[0], fenc(d0));
                atomicMax(&smax[1], fenc(d1));
                atomicMax(&smax[2], fenc(d2));
                atomicMax(&smax[3], fenc(d3));
            }
        }
    }
    __syncthreads();
    if (tid < 4) atomicMax(&g_gmaxenc[Lidx][tid], smax[tid]);
}

// ---------------- CSR build --------------------------------------------------
__global__ void zero_deg(int n) {
    int i = blockIdx.x * blockDim.x + threadIdx.x;
    if (i < n) g_deg[i] = 0;
}
__global__ void count_deg(const int* __restrict__ dst, int E) {
    int e = blockIdx.x * blockDim.x + threadIdx.x;
    if (e < E) atomicAdd(&g_deg[dst[e]], 1);
}
__global__ void scanA(int n) {
    __shared__ int sh[SCANB];
    int i = blockIdx.x * SCANB + threadIdx.x;
    int v = (i < n) ? g_deg[i] : 0;
    sh[threadIdx.x] = v;
    __syncthreads();
    for (int off = 1; off < SCANB; off <<= 1) {
        int t = (threadIdx.x >= off) ? sh[threadIdx.x - off] : 0;
        __syncthreads();
        sh[threadIdx.x] += t;
        __syncthreads();
    }
    if (i < n) g_rowptr[i] = sh[threadIdx.x] - v;
    if (threadIdx.x == SCANB - 1) g_bsum[blockIdx.x] = sh[SCANB - 1];
}
__global__ void scanB(int nb) {
    __shared__ int sh[256];
    int v = (threadIdx.x < nb) ? g_bsum[threadIdx.x] : 0;
    sh[threadIdx.x] = v;
    __syncthreads();
    for (int off = 1; off < 256; off <<= 1) {
        int t = (threadIdx.x >= off) ? sh[threadIdx.x - off] : 0;
        __syncthreads();
        sh[threadIdx.x] += t;
        __syncthreads();
    }
    if (threadIdx.x < nb) g_bsum[threadIdx.x] = sh[threadIdx.x] - v;
}
__global__ void scanC(int n, int E) {
    int i = blockIdx.x * blockDim.x + threadIdx.x;
    if (i < NG * DF) g_pool[i] = 0.f;
    if (i < NG) g_cnt[i] = 0;
    if (i < n) {
        int r = g_rowptr[i] + g_bsum[i / SCANB];
        g_rowptr[i] = r;
        g_pos[i] = r;
    }
    if (i == 0) g_rowptr[n] = E;
}
__global__ void csr_fill(const int* __restrict__ src, const int* __restrict__ dst, int E) {
    int e = blockIdx.x * blockDim.x + threadIdx.x;
    if (e >= E) return;
    int p = atomicAdd(&g_pos[dst[e]], 1);
    g_csr[p] = src[e];
}

// ---------------- fused per-node GAT (64-thr blocks) --------------------------
__global__ void gat_node(const float* __restrict__ bias, int n, int L, int last,
                         const int* __restrict__ batch, float* __restrict__ lastOut) {
    int wid = (blockIdx.x * blockDim.x + threadIdx.x) >> 5;
    int l = threadIdx.x & 31;
    if (wid >= n) return;
    int rp = g_rowptr[wid], re = g_rowptr[wid + 1];

    float4 ad = *(const float4*)&g_al[wid * 4];
    float4 bd = *(const float4*)&g_ar[wid * 4];

    int h = l >> 3;
    int eo = l & 7;
    float arh  = sel4(bd, h);
    float mh   = lrelu(fdec(g_gmaxenc[L][h]) + arh);
    float slgh = lrelu(sel4(ad, h) + arh);

    float zacc = 0.f;
    float4 acc = make_float4(0.f, 0.f, 0.f, 0.f);

    int s_cur = wid; float als_cur = 0.f;
    if (rp + eo < re) {
        s_cur = g_csr[rp + eo];
        als_cur = __ldg(&g_al[s_cur * 4 + h]);
    }
    for (int j0 = rp; j0 < re; j0 += 8) {
        int s_nxt = wid; float als_nxt = 0.f;
        if (j0 + 8 + eo < re) {
            s_nxt = g_csr[j0 + 8 + eo];
            als_nxt = __ldg(&g_al[s_nxt * 4 + h]);
        }
        float e_l = 0.f;
        if (j0 + eo < re) {
            e_l = __expf(lrelu(als_cur + arh) - mh);
            zacc += e_l;
        }
        int kmax = min(8, re - j0);
#pragma unroll 8
        for (int k = 0; k < kmax; k++) {
            int s = __shfl_sync(0xFFFFFFFFu, s_cur, k);
            float ek = __shfl_sync(0xFFFFFFFFu, e_l, (l & 24) | k);
            uint2 u = *(const uint2*)&g_XWh[s * 128 + 4 * l];
            __half2 p0 = *(__half2*)&u.x, p1 = *(__half2*)&u.y;
            float2 f0 = __half22float2(p0), f1 = __half22float2(p1);
            acc.x += ek * f0.x; acc.y += ek * f0.y;
            acc.z += ek * f1.x; acc.w += ek * f1.y;
        }
        s_cur = s_nxt; als_cur = als_nxt;
    }
#pragma unroll
    for (int o = 1; o < 8; o <<= 1) zacc += __shfl_xor_sync(0xFFFFFFFFu, zacc, o);

    float eself = __expf(slgh - mh);
    float rz = 1.f / (zacc + eself);
    uint2 us = *(const uint2*)&g_XWh[wid * 128 + 4 * l];
    __half2 s0 = *(__half2*)&us.x, s1 = *(__half2*)&us.y;
    float2 fs0 = __half22float2(s0), fs1 = __half22float2(s1);
    float4 bv = *(const float4*)&bias[4 * l];
    float4 o;
    o.x = fmaxf((acc.x + eself * fs0.x) * rz + bv.x, 0.f);
    o.y = fmaxf((acc.y + eself * fs0.y) * rz + bv.y, 0.f);
    o.z = fmaxf((acc.z + eself * fs1.x) * rz + bv.z, 0.f);
    o.w = fmaxf((acc.w + eself * fs1.y) * rz + bv.w, 0.f);

    if (!last) {
        __half2 h0 = __floats2half2_rn(o.x, o.y);
        __half2 h1 = __floats2half2_rn(o.z, o.w);
        uint2 u;
        u.x = *(uint32_t*)&h0; u.y = *(uint32_t*)&h1;
        stcs2u(&g_Hh[wid * 128 + 4 * l], u);
    } else {
        stcs4(&lastOut[wid * 128 + 4 * l], o);
        int b = batch[wid];
        redAdd4(&g_pool[b * 128 + 4 * l], o);
        if (l == 0) atomicAdd(&g_cnt[b], 1);
    }
}

// ---------------- MLP head ----------------------------------------------------
__global__ void mlp_kernel(const float* __restrict__ lin1w, const float* __restrict__ lin1b,
                           const float* __restrict__ lin2w, const float* __restrict__ lin2b,
                           float* __restrict__ out) {
    __shared__ float pr[128];
    __shared__ float gg[128];
    __shared__ float lo[NCLS];
    int gr = blockIdx.x;
    int c = threadIdx.x;
    float cnt = (float)max(g_cnt[gr], 1);
    pr[c] = g_pool[gr * 128 + c] / cnt;
    __syncthreads();
    float acc = lin1b[c];
#pragma unroll 8
    for (int k = 0; k < 128; k++) acc += pr[k] * lin1w[k * 128 + c];
    gg[c] = fmaxf(acc, 0.f);
    __syncthreads();
    if (c < NCLS) {
        float a = lin2b[c];
#pragma unroll 8
        for (int k = 0; k < 128; k++) a += gg[k] * lin2w[k * NCLS + c];
        lo[c] = a;
    }
    __syncthreads();
    if (c == 0) {
        float mx = lo[0];
#pragma unroll
        for (int j = 1; j < NCLS; j++) mx = fmaxf(mx, lo[j]);
        float s = 0.f;
#pragma unroll
        for (int j = 0; j < NCLS; j++) s += expf(lo[j] - mx);
        float lse = mx + logf(s);
#pragma unroll
        for (int j = 0; j < NCLS; j++) out[gr * NCLS + j] = lo[j] - lse;
    }
}

// ---------------- host launcher ---------------------------------------------
extern "C" void kernel_launch(void* const* d_in, const int* in_sizes, int n_in,
                              void* d_out, int out_size) {
    const float* x    = (const float*)d_in[0];
    const int*   eidx = (const int*)d_in[1];
    const int*   batch= (const int*)d_in[2];
    const float* W[3]  = { (const float*)d_in[3], (const float*)d_in[7],  (const float*)d_in[11] };
    const float* al[3] = { (const float*)d_in[4], (const float*)d_in[8],  (const float*)d_in[12] };
    const float* ar[3] = { (const float*)d_in[5], (const float*)d_in[9],  (const float*)d_in[13] };
    const float* bb[3] = { (const float*)d_in[6], (const float*)d_in[10], (const float*)d_in[14] };
    const float* lin1w = (const float*)d_in[15];
    const float* lin1b = (const float*)d_in[16];
    const float* lin2w = (const float*)d_in[17];
    const float* lin2b = (const float*)d_in[18];

    int n = in_sizes[0] / DF;
    int E = in_sizes[1] / 2;
    const int* src = eidx;
    const int* dst = eidx + E;

    float* out_logits = (float*)d_out;
    float* out_last   = (float*)d_out + NG * NCLS;

    __half* hh; cudaGetSymbolAddress((void**)&hh, g_Hh);
    uint4* wf; cudaGetSymbolAddress((void**)&wf, g_WfT);

    static int inited = 0;
    static cudaStream_t sB;
    static cudaEvent_t evF, evJ;
    if (!inited) {
        cudaFuncSetAttribute(gemm_mma, cudaFuncAttributeMaxDynamicSharedMemorySize, GS_TOT);
        cudaStreamCreateWithFlags(&sB, cudaStreamNonBlocking);
        cudaEventCreateWithFlags(&evF, cudaEventDisableTiming);
        cudaEventCreateWithFlags(&evJ, cudaEventDisableTiming);
        inited = 1;
    }

    int gatB   = (n * 32 + 63) / 64;     // 64-thr blocks: finest tail granularity
    int edgeTB = (E + 255) / 256;
    int nodeTB = (n + 255) / 256;
    int nScanB = (n + SCANB - 1) / SCANB;
    int gemmB  = (n + 63) / 64;

    prep_all<<<24, 256>>>(W[0], W[1], W[2]);                              // 0
    cudaEventRecord(evF, 0);
    cudaStreamWaitEvent(sB, evF, 0);
    zero_deg<<<nodeTB, 256, 0, sB>>>(n);                                  // 1
    count_deg<<<edgeTB, 256, 0, sB>>>(dst, E);                            // 2
    gemm_mma<<<gemmB, 256, GS_TOT>>>(x, 0, wf, al[0], ar[0], n, 0);       // 3 <- profiled
    scanA<<<nScanB, SCANB, 0, sB>>>(n);                                   // 4
    scanB<<<1, 256, 0, sB>>>(nScanB);                                     // 5
    scanC<<<nodeTB, 256, 0, sB>>>(n, E);                                  // 6
    csr_fill<<<edgeTB, 256, 0, sB>>>(src, dst, E);                        // 7

    cudaEventRecord(evJ, sB);
    cudaStreamWaitEvent(0, evJ, 0);

    gat_node<<<gatB, 64>>>(bb[0], n, 0, 0, batch, out_last);
    for (int L = 1; L < 3; L++) {
        gemm_mma<<<gemmB, 256, GS_TOT>>>(hh, 1, wf + L * 2048, al[L], ar[L], n, L);
        gat_node<<<gatB, 64>>>(bb[L], n, L, (L == 2) ? 1 : 0, batch, out_last);
    }

    mlp_kernel<<<NG, 128>>>(lin1w, lin1b, lin2w, lin2b, out_logits);
}

// round 16
// speedup vs baseline: 1.2592x; 1.0650x over previous
#include <cuda_runtime.h>
#include <cuda_bf16.h>
#include <cuda_fp16.h>
#include <cstdint>
#include <math.h>

#define NND 100000
#define NE  1600000
#define DF  128
#define HEADS 4
#define NG  64
#define NCLS 10
#define NEG 0.2f
#define SCANB 512
#define DBINS 256

// ---------------- scratch ----------------------------------------------------
__device__ __align__(16) __half g_XWh[NND * DF];
__device__ __align__(16) __half g_Hh [NND * DF];
__device__ __align__(16) float  g_al[NND * HEADS];
__device__ __align__(16) float  g_ar[NND * HEADS];
__device__ unsigned g_gmaxenc[3][HEADS];
__device__ int   g_deg[NND];
__device__ int   g_rowptr[NND + 1];
__device__ int   g_pos[NND];
__device__ int   g_bsum[(NND + SCANB - 1) / SCANB];
__device__ int   g_csr[NE];
__device__ int   g_hist[DBINS];
__device__ int   g_order[NND];          // nodes in descending-degree order
__device__ float g_pool[NG * DF];
__device__ int   g_cnt[NG];
__device__ __align__(16) uint4 g_WfT[3][2048];

// ---------------- helpers ----------------------------------------------------
__device__ __forceinline__ float lrelu(float x) { return x > 0.f ? x : NEG * x; }
__device__ __forceinline__ unsigned fenc(float f) {
    unsigned u = __float_as_uint(f);
    return (u & 0x80000000u) ? ~u : (u | 0x80000000u);
}
__device__ __forceinline__ float fdec(unsigned u) {
    return (u & 0x80000000u) ? __uint_as_float(u & 0x7FFFFFFFu)
                             : __uint_as_float(~u);
}
__device__ __forceinline__ float sel4(float4 v, int h) {
    return h == 0 ? v.x : h == 1 ? v.y : h == 2 ? v.z : v.w;
}
__device__ __forceinline__ void redAdd4(float* p, float4 v) {
    asm volatile("red.global.add.v4.f32 [%0], {%1,%2,%3,%4};"
                 :: "l"(p), "f"(v.x), "f"(v.y), "f"(v.z), "f"(v.w) : "memory");
}
__device__ __forceinline__ void stcs4(float* p, float4 v) {
    asm volatile("st.global.cs.v4.f32 [%0], {%1,%2,%3,%4};"
                 :: "l"(p), "f"(v.x), "f"(v.y), "f"(v.z), "f"(v.w) : "memory");
}
__device__ __forceinline__ void stcs2u(void* p, uint2 u) {
    asm volatile("st.global.cs.v2.u32 [%0], {%1,%2};"
                 :: "l"(p), "r"(u.x), "r"(u.y) : "memory");
}
__device__ __forceinline__ uint32_t smem_u32(const void* p) {
    uint32_t a;
    asm("{ .reg .u64 t; cvta.to.shared.u64 t, %1; cvt.u32.u64 %0, t; }" : "=r"(a) : "l"(p));
    return a;
}
__device__ __forceinline__ void ldm4(uint32_t& r0, uint32_t& r1, uint32_t& r2,
                                     uint32_t& r3, uint32_t addr) {
    asm volatile("ldmatrix.sync.aligned.m8n8.x4.shared.b16 {%0,%1,%2,%3}, [%4];"
                 : "=r"(r0), "=r"(r1), "=r"(r2), "=r"(r3) : "r"(addr));
}
__device__ __forceinline__ void mma16816f(float* d, uint32_t a0, uint32_t a1,
                                          uint32_t a2, uint32_t a3,
                                          uint32_t b0, uint32_t b1) {
    asm volatile(
        "mma.sync.aligned.m16n8k16.row.col.f32.f16.f16.f32 "
        "{%0,%1,%2,%3}, {%4,%5,%6,%7}, {%8,%9}, {%0,%1,%2,%3};"
        : "+f"(d[0]), "+f"(d[1]), "+f"(d[2]), "+f"(d[3])
        : "r"(a0), "r"(a1), "r"(a2), "r"(a3), "r"(b0), "r"(b1));
}

union H16x8 { __half h[8]; uint4 u; };

// ---------------- weight prep + gmax zero -------------------------------------
__global__ void prep_all(const float* __restrict__ W0, const float* __restrict__ W1,
                         const float* __restrict__ W2) {
    if (blockIdx.x == 0 && threadIdx.x < 12)
        ((unsigned*)g_gmaxenc)[threadIdx.x] = 0u;
    int L = blockIdx.x >> 3;
    int i = (blockIdx.x & 7) * 256 + threadIdx.x;
    const float* W = (L == 0) ? W0 : (L == 1) ? W1 : W2;
    int nn = i >> 4, c = i & 15;
    H16x8 F;
#pragma unroll
    for (int j = 0; j < 8; j++)
        F.h[j] = __float2half(W[(c * 8 + j) * 128 + nn]);
    g_WfT[L][nn * 16 + (c ^ (nn & 7))] = F.u;
}

// ---------------- fp16 HMMA GEMM + fused al/ar + almax -----------------------
#define GS_A   0
#define GS_W   16384
#define GS_ATT 49152
#define GS_TOT 50176
#define HS_STRIDE 136

__global__ void __launch_bounds__(256, 3) gemm_mma(
    const void* __restrict__ Ain, int aHalf, const uint4* __restrict__ WfT,
    const float* __restrict__ attl, const float* __restrict__ attr,
    int n, int Lidx) {
    extern __shared__ char smem[];
    __shared__ unsigned smax[4];
    uint32_t sb = smem_u32(smem);
    int tid = threadIdx.x, w = tid >> 5, l = tid & 31;
    int rg = w & 3, ch = w >> 2;
    int row0 = blockIdx.x * 64;

    {
        uint4* wf = (uint4*)(smem + GS_W);
        for (int i = tid; i < 2048; i += 256) wf[i] = WfT[i];
    }
    if (aHalf) {
        const __half* Ah = (const __half*)Ain;
        for (int i = tid; i < 1024; i += 256) {
            int r = i >> 4, c = i & 15;
            int row = row0 + r;
            uint4 u = make_uint4(0u, 0u, 0u, 0u);
            if (row < n) u = __ldcs((const uint4*)&Ah[row * 128 + c * 8]);
            *(uint4*)(smem + GS_A + r * 256 + ((c ^ (r & 7)) << 4)) = u;
        }
    } else {
        const float* A = (const float*)Ain;
        for (int i = tid; i < 1024; i += 256) {
            int r = i >> 4, c = i & 15;
            int row = row0 + r;
            float4 v0 = make_float4(0.f, 0.f, 0.f, 0.f), v1 = v0;
            if (row < n) {
                v0 = __ldcs((const float4*)&A[row * 128 + c * 8]);
                v1 = __ldcs((const float4*)&A[row * 128 + c * 8 + 4]);
            }
            H16x8 F;
            F.h[0] = __float2half(v0.x); F.h[1] = __float2half(v0.y);
            F.h[2] = __float2half(v0.z); F.h[3] = __float2half(v0.w);
            F.h[4] = __float2half(v1.x); F.h[5] = __float2half(v1.y);
            F.h[6] = __float2half(v1.z); F.h[7] = __float2half(v1.w);
            *(uint4*)(smem + GS_A + r * 256 + ((c ^ (r & 7)) << 4)) = F.u;
        }
    }
    __syncthreads();

    int aRow = rg * 16 + ((l >> 3) & 1) * 8 + (l & 7);
    int aChk = (l >> 4) & 1;
    uint32_t aBase = sb + GS_A + aRow * 256;
    int aXor = aRow & 7;
    int bRowL = ((l >> 4) & 1) * 8 + (l & 7);
    int bChk = (l >> 3) & 1;

    float acc[32];
#pragma unroll
    for (int i = 0; i < 32; i++) acc[i] = 0.f;

#pragma unroll
    for (int ks = 0; ks < 8; ks++) {
        uint32_t a0, a1, a2, a3;
        ldm4(a0, a1, a2, a3, aBase + (((2 * ks + aChk) ^ aXor) << 4));
#pragma unroll
        for (int p = 0; p < 4; p++) {
            int bRow = ch * 64 + p * 16 + bRowL;
            uint32_t bAddr = sb + GS_W + bRow * 256
                           + (((2 * ks + bChk) ^ (bRow & 7)) << 4);
            uint32_t b0, b1, b2, b3;
            ldm4(b0, b1, b2, b3, bAddr);
            mma16816f(&acc[(2 * p) * 4],     a0, a1, a2, a3, b0, b1);
            mma16816f(&acc[(2 * p + 1) * 4], a0, a1, a2, a3, b2, b3);
        }
    }
    __syncthreads();

    __half* Hs = (__half*)smem;
    float* att = (float*)(smem + GS_ATT);
    att[tid] = (tid < 128) ? attl[tid] : attr[tid - 128];
    if (tid < 4) smax[tid] = 0u;
    {
        int r1 = rg * 16 + (l >> 2);
#pragma unroll
        for (int nt = 0; nt < 8; nt++) {
            int p = nt >> 1, t = nt & 1;
            int col = ch * 64 + p * 16 + t * 8 + (l & 3) * 2;
            float* d = &acc[nt * 4];
            __half2 lo = __floats2half2_rn(d[0], d[1]);
            __half2 hi = __floats2half2_rn(d[2], d[3]);
            *(__half2*)&Hs[r1 * HS_STRIDE + col]       = lo;
            *(__half2*)&Hs[(r1 + 8) * HS_STRIDE + col] = hi;
        }
    }
    __syncthreads();

    for (int i = tid; i < 1024; i += 256) {
        int r = i >> 4, c = i & 15;
        int row = row0 + r;
        if (row < n)
            *(uint4*)&g_XWh[row * 128 + c * 8] =
                *(uint4*)&Hs[r * HS_STRIDE + c * 8];
    }
    if (tid < 128) {
        int half_ = tid >> 6;
        int r = tid & 63;
        int row = row0 + r;
        if (row < n) {
            const float* av = att + half_ * 128;
            const __half2* hr = (const __half2*)&Hs[r * HS_STRIDE];
            float d0 = 0.f, d1 = 0.f, d2 = 0.f, d3 = 0.f;
#pragma unroll 8
            for (int c = 0; c < 16; c++) {
                float2 f0 = __half22float2(hr[c]);
                float2 f1 = __half22float2(hr[16 + c]);
                float2 f2 = __half22float2(hr[32 + c]);
                float2 f3 = __half22float2(hr[48 + c]);
                d0 += f0.x * av[2 * c]      + f0.y * av[2 * c + 1];
                d1 += f1.x * av[32 + 2 * c] + f1.y * av[32 + 2 * c + 1];
                d2 += f2.x * av[64 + 2 * c] + f2.y * av[64 + 2 * c + 1];
                d3 += f3.x * av[96 + 2 * c] + f3.y * av[96 + 2 * c + 1];
            }
            float* dst = half_ ? g_ar : g_al;
            *(float4*)&dst[row * 4] = make_float4(d0, d1, d2, d3);
            if (half_ == 0) {
                atomicMax(&smax[0], fenc(d0));
                atomicMax(&smax[1], fenc(d1));
                atomicMax(&smax[2], fenc(d2));
                atomicMax(&smax[3], fenc(d3));
            }
        }
    }
    __syncthreads();
    if (tid < 4) atomicMax(&g_gmaxenc[Lidx][tid], smax[tid]);
}

// ---------------- CSR build + degree-order ------------------------------------
__global__ void zero_deg(int n) {
    int i = blockIdx.x * blockDim.x + threadIdx.x;
    if (i < n) g_deg[i] = 0;
    if (i < DBINS) g_hist[i] = 0;
}
__global__ void count_deg(const int* __restrict__ dst, int E) {
    int e = blockIdx.x * blockDim.x + threadIdx.x;
    if (e < E) atomicAdd(&g_deg[dst[e]], 1);
}
__global__ void hist_count(int n) {
    int i = blockIdx.x * blockDim.x + threadIdx.x;
    if (i >= n) return;
    int key = DBINS - 1 - min(g_deg[i], DBINS - 1);   // descending degree
    atomicAdd(&g_hist[key], 1);
}
__global__ void hist_scan() {    // 256 bins, one block
    __shared__ int sh[DBINS];
    int t = threadIdx.x;
    int v = g_hist[t];
    sh[t] = v;
    __syncthreads();
    for (int off = 1; off < DBINS; off <<= 1) {
        int u = (t >= off) ? sh[t - off] : 0;
        __syncthreads();
        sh[t] += u;
        __syncthreads();
    }
    g_hist[t] = sh[t] - v;       // exclusive prefix
}
__global__ void order_scatter(int n) {
    int i = blockIdx.x * blockDim.x + threadIdx.x;
    if (i >= n) return;
    int key = DBINS - 1 - min(g_deg[i], DBINS - 1);
    int p = atomicAdd(&g_hist[key], 1);
    g_order[p] = i;
}
__global__ void scanA(int n) {
    __shared__ int sh[SCANB];
    int i = blockIdx.x * SCANB + threadIdx.x;
    int v = (i < n) ? g_deg[i] : 0;
    sh[threadIdx.x] = v;
    __syncthreads();
    for (int off = 1; off < SCANB; off <<= 1) {
        int t = (threadIdx.x >= off) ? sh[threadIdx.x - off] : 0;
        __syncthreads();
        sh[threadIdx.x] += t;
        __syncthreads();
    }
    if (i < n) g_rowptr[i] = sh[threadIdx.x] - v;
    if (threadIdx.x == SCANB - 1) g_bsum[blockIdx.x] = sh[SCANB - 1];
}
__global__ void scanB(int nb) {
    __shared__ int sh[256];
    int v = (threadIdx.x < nb) ? g_bsum[threadIdx.x] : 0;
    sh[threadIdx.x] = v;
    __syncthreads();
    for (int off = 1; off < 256; off <<= 1) {
        int t = (threadIdx.x >= off) ? sh[threadIdx.x - off] : 0;
        __syncthreads();
        sh[threadIdx.x] += t;
        __syncthreads();
    }
    if (threadIdx.x < nb) g_bsum[threadIdx.x] = sh[threadIdx.x] - v;
}
__global__ void scanC(int n, int E) {
    int i = blockIdx.x * blockDim.x + threadIdx.x;
    if (i < NG * DF) g_pool[i] = 0.f;
    if (i < NG) g_cnt[i] = 0;
    if (i < n) {
        int r = g_rowptr[i] + g_bsum[i / SCANB];
        g_rowptr[i] = r;
        g_pos[i] = r;
    }
    if (i == 0) g_rowptr[n] = E;
}
__global__ void csr_fill(const int* __restrict__ src, const int* __restrict__ dst, int E) {
    int e = blockIdx.x * blockDim.x + threadIdx.x;
    if (e >= E) return;
    int p = atomicAdd(&g_pos[dst[e]], 1);
    g_csr[p] = src[e];
}

// ---------------- fused per-node GAT (64-thr, LPT order) ----------------------
__global__ void gat_node(const float* __restrict__ bias, int n, int L, int last,
                         const int* __restrict__ batch, float* __restrict__ lastOut) {
    int widx = (blockIdx.x * blockDim.x + threadIdx.x) >> 5;
    int l = threadIdx.x & 31;
    if (widx >= n) return;
    int wid = g_order[widx];           // descending-degree schedule
    int rp = g_rowptr[wid], re = g_rowptr[wid + 1];

    float4 ad = *(const float4*)&g_al[wid * 4];
    float4 bd = *(const float4*)&g_ar[wid * 4];

    int h = l >> 3;
    int eo = l & 7;
    float arh  = sel4(bd, h);
    float mh   = lrelu(fdec(g_gmaxenc[L][h]) + arh);
    float slgh = lrelu(sel4(ad, h) + arh);

    float zacc = 0.f;
    float4 acc = make_float4(0.f, 0.f, 0.f, 0.f);

    int s_cur = wid; float als_cur = 0.f;
    if (rp + eo < re) {
        s_cur = g_csr[rp + eo];
        als_cur = __ldg(&g_al[s_cur * 4 + h]);
    }
    for (int j0 = rp; j0 < re; j0 += 8) {
        int s_nxt = wid; float als_nxt = 0.f;
        if (j0 + 8 + eo < re) {
            s_nxt = g_csr[j0 + 8 + eo];
            als_nxt = __ldg(&g_al[s_nxt * 4 + h]);
        }
        float e_l = 0.f;
        if (j0 + eo < re) {
            e_l = __expf(lrelu(als_cur + arh) - mh);
            zacc += e_l;
        }
        int kmax = min(8, re - j0);
#pragma unroll 8
        for (int k = 0; k < kmax; k++) {
            int s = __shfl_sync(0xFFFFFFFFu, s_cur, k);
            float ek = __shfl_sync(0xFFFFFFFFu, e_l, (l & 24) | k);
            uint2 u = *(const uint2*)&g_XWh[s * 128 + 4 * l];
            __half2 p0 = *(__half2*)&u.x, p1 = *(__half2*)&u.y;
            float2 f0 = __half22float2(p0), f1 = __half22float2(p1);
            acc.x += ek * f0.x; acc.y += ek * f0.y;
            acc.z += ek * f1.x; acc.w += ek * f1.y;
        }
        s_cur = s_nxt; als_cur = als_nxt;
    }
#pragma unroll
    for (int o = 1; o < 8; o <<= 1) zacc += __shfl_xor_sync(0xFFFFFFFFu, zacc, o);

    float eself = __expf(slgh - mh);
    float rz = 1.f / (zacc + eself);
    uint2 us = *(const uint2*)&g_XWh[wid * 128 + 4 * l];
    __half2 s0 = *(__half2*)&us.x, s1 = *(__half2*)&us.y;
    float2 fs0 = __half22float2(s0), fs1 = __half22float2(s1);
    float4 bv = *(const float4*)&bias[4 * l];
    float4 o;
    o.x = fmaxf((acc.x + eself * fs0.x) * rz + bv.x, 0.f);
    o.y = fmaxf((acc.y + eself * fs0.y) * rz + bv.y, 0.f);
    o.z = fmaxf((acc.z + eself * fs1.x) * rz + bv.z, 0.f);
    o.w = fmaxf((acc.w + eself * fs1.y) * rz + bv.w, 0.f);

    if (!last) {
        __half2 h0 = __floats2half2_rn(o.x, o.y);
        __half2 h1 = __floats2half2_rn(o.z, o.w);
        uint2 u;
        u.x = *(uint32_t*)&h0; u.y = *(uint32_t*)&h1;
        stcs2u(&g_Hh[wid * 128 + 4 * l], u);
    } else {
        stcs4(&lastOut[wid * 128 + 4 * l], o);
        int b = batch[wid];
        redAdd4(&g_pool[b * 128 + 4 * l], o);
        if (l == 0) atomicAdd(&g_cnt[b], 1);
    }
}

// ---------------- MLP head ----------------------------------------------------
__global__ void mlp_kernel(const float* __restrict__ lin1w, const float* __restrict__ lin1b,
                           const float* __restrict__ lin2w, const float* __restrict__ lin2b,
                           float* __restrict__ out) {
    __shared__ float pr[128];
    __shared__ float gg[128];
    __shared__ float lo[NCLS];
    int gr = blockIdx.x;
    int c = threadIdx.x;
    float cnt = (float)max(g_cnt[gr], 1);
    pr[c] = g_pool[gr * 128 + c] / cnt;
    __syncthreads();
    float acc = lin1b[c];
#pragma unroll 8
    for (int k = 0; k < 128; k++) acc += pr[k] * lin1w[k * 128 + c];
    gg[c] = fmaxf(acc, 0.f);
    __syncthreads();
    if (c < NCLS) {
        float a = lin2b[c];
#pragma unroll 8
        for (int k = 0; k < 128; k++) a += gg[k] * lin2w[k * NCLS + c];
        lo[c] = a;
    }
    __syncthreads();
    if (c == 0) {
        float mx = lo[0];
#pragma unroll
        for (int j = 1; j < NCLS; j++) mx = fmaxf(mx, lo[j]);
        float s = 0.f;
#pragma unroll
        for (int j = 0; j < NCLS; j++) s += expf(lo[j] - mx);
        float lse = mx + logf(s);
#pragma unroll
        for (int j = 0; j < NCLS; j++) out[gr * NCLS + j] = lo[j] - lse;
    }
}

// ---------------- host launcher ---------------------------------------------
extern "C" void kernel_launch(void* const* d_in, const int* in_sizes, int n_in,
                              void* d_out, int out_size) {
    const float* x    = (const float*)d_in[0];
    const int*   eidx = (const int*)d_in[1];
    const int*   batch= (const int*)d_in[2];
    const float* W[3]  = { (const float*)d_in[3], (const float*)d_in[7],  (const float*)d_in[11] };
    const float* al[3] = { (const float*)d_in[4], (const float*)d_in[8],  (const float*)d_in[12] };
    const float* ar[3] = { (const float*)d_in[5], (const float*)d_in[9],  (const float*)d_in[13] };
    const float* bb[3] = { (const float*)d_in[6], (const float*)d_in[10], (const float*)d_in[14] };
    const float* lin1w = (const float*)d_in[15];
    const float* lin1b = (const float*)d_in[16];
    const float* lin2w = (const float*)d_in[17];
    const float* lin2b = (const float*)d_in[18];

    int n = in_sizes[0] / DF;
    int E = in_sizes[1] / 2;
    const int* src = eidx;
    const int* dst = eidx + E;

    float* out_logits = (float*)d_out;
    float* out_last   = (float*)d_out + NG * NCLS;

    __half* hh; cudaGetSymbolAddress((void**)&hh, g_Hh);
    uint4* wf; cudaGetSymbolAddress((void**)&wf, g_WfT);

    static int inited = 0;
    static cudaStream_t sB;
    static cudaEvent_t evF, evJ;
    if (!inited) {
        cudaFuncSetAttribute(gemm_mma, cudaFuncAttributeMaxDynamicSharedMemorySize, GS_TOT);
        cudaStreamCreateWithFlags(&sB, cudaStreamNonBlocking);
        cudaEventCreateWithFlags(&evF, cudaEventDisableTiming);
        cudaEventCreateWithFlags(&evJ, cudaEventDisableTiming);
        inited = 1;
    }

    int gatB   = (n * 32 + 63) / 64;
    int edgeTB = (E + 255) / 256;
    int nodeTB = (n + 255) / 256;
    int nScanB = (n + SCANB - 1) / SCANB;
    int gemmB  = (n + 63) / 64;

    prep_all<<<24, 256>>>(W[0], W[1], W[2]);                              // 0
    cudaEventRecord(evF, 0);
    cudaStreamWaitEvent(sB, evF, 0);
    zero_deg<<<nodeTB, 256, 0, sB>>>(n);                                  // 1
    count_deg<<<edgeTB, 256, 0, sB>>>(dst, E);                            // 2
    gemm_mma<<<gemmB, 256, GS_TOT>>>(x, 0, wf, al[0], ar[0], n, 0);       // 3 <- profiled
    scanA<<<nScanB, SCANB, 0, sB>>>(n);                                   // 4
    scanB<<<1, 256, 0, sB>>>(nScanB);                                     // 5
    scanC<<<nodeTB, 256, 0, sB>>>(n, E);                                  // 6
    csr_fill<<<edgeTB, 256, 0, sB>>>(src, dst, E);                        // 7
    hist_count<<<nodeTB, 256, 0, sB>>>(n);                                // 8
    hist_scan<<<1, DBINS, 0, sB>>>();                                     // 9
    order_scatter<<<nodeTB, 256, 0, sB>>>(n);                             // 10

    cudaEventRecord(evJ, sB);
    cudaStreamWaitEvent(0, evJ, 0);

    gat_node<<<gatB, 64>>>(bb[0], n, 0, 0, batch, out_last);
    for (int L = 1; L < 3; L++) {
        gemm_mma<<<gemmB, 256, GS_TOT>>>(hh, 1, wf + L * 2048, al[L], ar[L], n, L);
        gat_node<<<gatB, 64>>>(bb[L], n, L, (L == 2) ? 1 : 0, batch, out_last);
    }

    mlp_kernel<<<NG, 128>>>(lin1w, lin1b, lin2w, lin2b, out_logits);
}